// round 3
// baseline (speedup 1.0000x reference)
#include <cuda_runtime.h>

// ---------------------------------------------------------------------------
// Fused spatio-temporal GCN layer, one CTA per (b, t).
//   stage 0: load x slice (t-1..t+1) + all small weights into smem
//   stage 1: temporal conv + ReLU -> Tm[170][64] (smem)
//   stage 2: V_k[m][o] = sum_c Tm[m][c] * theta_k[c][o]  (smem, 3x170x64)
//   stage 3: gcn[n][o] = sum_{k,m} cheb_k[n][m] * V_k[m][o]; out = relu(gcn)+res
// Inner GEMM loops use packed fma.rn.f32x2 (2x fp32 FMA rate on Blackwell).
// ---------------------------------------------------------------------------

#define Bq   16
#define FINq 3
#define NV   170
#define TTq  288
#define HH   64
#define OO   64
#define KK   3

typedef unsigned long long ull;

__device__ __forceinline__ ull f2fma(ull a, ull b, ull c) {
    ull d;
    asm("fma.rn.f32x2 %0, %1, %2, %3;" : "=l"(d) : "l"(a), "l"(b), "l"(c));
    return d;
}
__device__ __forceinline__ ull f2dup(float a) {
    ull d;
    asm("mov.b64 %0, {%1, %1};" : "=l"(d) : "f"(a));
    return d;
}
__device__ __forceinline__ float2 f2un(ull p) {
    float2 r;
    asm("mov.b64 {%0, %1}, %2;" : "=f"(r.x), "=f"(r.y) : "l"(p));
    return r;
}

// shared memory layout (float offsets)
#define XS_OFF   0                      // 3*3*170 = 1530  (x slice: [f][s][m])
#define WC_OFF   1530                   // conv_w 64*3*3 = 576
#define WCB_OFF  2106                   // conv_b 64
#define WRES_OFF 2170                   // res_w 64*3 = 192
#define WRB_OFF  2362                   // res_b 64
#define TM_OFF   2432                   // Tm 170*64 = 10880 (16B aligned)
#define V_OFF    (TM_OFF + NV*HH)       // 13312; V 3*170*64 = 32640
#define SMEM_FLOATS (V_OFF + KK*NV*OO)  // 45952
#define SMEM_BYTES  (SMEM_FLOATS * 4)   // 183808 bytes

__global__ void __launch_bounds__(256, 1)
stgcn_fused_kernel(const float* __restrict__ x,
                   const float* __restrict__ cheb,
                   const float* __restrict__ conv_w,
                   const float* __restrict__ conv_b,
                   const float* __restrict__ theta,
                   const float* __restrict__ res_w,
                   const float* __restrict__ res_b,
                   float* __restrict__ out)
{
    extern __shared__ float sm[];
    float* xs   = sm + XS_OFF;
    float* wc   = sm + WC_OFF;
    float* wcb  = sm + WCB_OFF;
    float* wres = sm + WRES_OFF;
    float* wrb  = sm + WRB_OFF;
    float* Tm   = sm + TM_OFF;
    float* Vv   = sm + V_OFF;

    const int t   = blockIdx.x;   // timestep
    const int b   = blockIdx.y;   // batch
    const int tid = threadIdx.x;

    // ---------------- stage 0: smem loads ----------------
    for (int i = tid; i < FINq * 3 * NV; i += 256) {
        int f = i / (3 * NV);
        int r = i - f * (3 * NV);
        int s = r / NV;
        int m = r - s * NV;
        int tt = t + s - 1;
        float v = 0.0f;
        if (tt >= 0 && tt < TTq)
            v = x[((size_t)(b * FINq + f) * NV + m) * TTq + tt];
        xs[i] = v;                       // layout (f*3+s)*NV + m
    }
    for (int i = tid; i < HH * FINq * 3; i += 256) wc[i] = conv_w[i];
    for (int i = tid; i < OO * FINq;     i += 256) wres[i] = res_w[i];
    if (tid < HH)                       wcb[tid]       = conv_b[tid];
    else if (tid >= 64 && tid < 128)    wrb[tid - 64]  = res_b[tid - 64];
    __syncthreads();

    // ---------------- stage 1: temporal conv + ReLU ----------------
    for (int idx = tid; idx < NV * HH; idx += 256) {
        int m = idx >> 6;
        int c = idx & 63;
        float v = wcb[c];
        #pragma unroll
        for (int f = 0; f < FINq; ++f)
            #pragma unroll
            for (int s = 0; s < 3; ++s)
                v = fmaf(xs[(f * 3 + s) * NV + m], wc[(c * FINq + f) * 3 + s], v);
        Tm[idx] = fmaxf(v, 0.0f);       // Tm[m*64 + c]
    }
    __syncthreads();

    const int tcol = tid & 7;           // 8 column-groups of 8 outputs
    const int trow = tid >> 3;          // 32 row-groups of 4 rows
    const int o8   = tcol * 8;

    // ---------------- stage 2: V_k = Tm @ theta_k ----------------
    for (int pass = 0; pass < 2; ++pass) {
        int m0 = pass * 128 + trow * 4;
        if (m0 >= NV) break;
        int  mi[4];
        bool mv[4];
        #pragma unroll
        for (int i = 0; i < 4; ++i) {
            mv[i] = (m0 + i) < NV;
            mi[i] = mv[i] ? (m0 + i) : (NV - 1);
        }
        for (int k = 0; k < KK; ++k) {
            ull acc[4][4];
            #pragma unroll
            for (int i = 0; i < 4; ++i)
                #pragma unroll
                for (int p = 0; p < 4; ++p) acc[i][p] = 0ull;

            const float* th = theta + (size_t)k * HH * OO + o8;
            #pragma unroll 4
            for (int c = 0; c < HH; ++c) {
                ulonglong2 ta = *(const ulonglong2*)(th + (size_t)c * OO);
                ulonglong2 tb = *(const ulonglong2*)(th + (size_t)c * OO + 4);
                #pragma unroll
                for (int i = 0; i < 4; ++i) {
                    ull aa = f2dup(Tm[mi[i] * HH + c]);
                    acc[i][0] = f2fma(aa, ta.x, acc[i][0]);
                    acc[i][1] = f2fma(aa, ta.y, acc[i][1]);
                    acc[i][2] = f2fma(aa, tb.x, acc[i][2]);
                    acc[i][3] = f2fma(aa, tb.y, acc[i][3]);
                }
            }
            #pragma unroll
            for (int i = 0; i < 4; ++i) {
                if (!mv[i]) continue;
                ulonglong2* dst =
                    (ulonglong2*)(Vv + ((size_t)k * NV + mi[i]) * OO + o8);
                dst[0] = make_ulonglong2(acc[i][0], acc[i][1]);
                dst[1] = make_ulonglong2(acc[i][2], acc[i][3]);
            }
        }
    }
    __syncthreads();

    // ---------------- stage 3: gcn = sum_k cheb_k @ V_k; epilogue ----------------
    for (int pass = 0; pass < 2; ++pass) {
        int n0 = pass * 128 + trow * 4;
        if (n0 >= NV) break;
        int  ni[4];
        bool nvld[4];
        #pragma unroll
        for (int i = 0; i < 4; ++i) {
            nvld[i] = (n0 + i) < NV;
            ni[i]   = nvld[i] ? (n0 + i) : (NV - 1);
        }

        ull acc[4][4];
        #pragma unroll
        for (int i = 0; i < 4; ++i)
            #pragma unroll
            for (int p = 0; p < 4; ++p) acc[i][p] = 0ull;

        for (int k = 0; k < KK; ++k) {
            const float* ch = cheb + (size_t)k * NV * NV;
            const float* vk = Vv + (size_t)k * NV * OO + o8;
            for (int m = 0; m < NV; m += 2) {
                ull cp[4];
                #pragma unroll
                for (int i = 0; i < 4; ++i)
                    cp[i] = *(const ull*)(ch + (size_t)ni[i] * NV + m); // 8B aligned: 170*4=680, m even

                const float* vp = vk + (size_t)m * OO;
                ulonglong2 v0a = *(const ulonglong2*)(vp);
                ulonglong2 v0b = *(const ulonglong2*)(vp + 4);
                ulonglong2 v1a = *(const ulonglong2*)(vp + OO);
                ulonglong2 v1b = *(const ulonglong2*)(vp + OO + 4);

                #pragma unroll
                for (int i = 0; i < 4; ++i) {
                    float2 cc = f2un(cp[i]);
                    ull a0 = f2dup(cc.x);
                    ull a1 = f2dup(cc.y);
                    acc[i][0] = f2fma(a0, v0a.x, acc[i][0]);
                    acc[i][1] = f2fma(a0, v0a.y, acc[i][1]);
                    acc[i][2] = f2fma(a0, v0b.x, acc[i][2]);
                    acc[i][3] = f2fma(a0, v0b.y, acc[i][3]);
                    acc[i][0] = f2fma(a1, v1a.x, acc[i][0]);
                    acc[i][1] = f2fma(a1, v1a.y, acc[i][1]);
                    acc[i][2] = f2fma(a1, v1b.x, acc[i][2]);
                    acc[i][3] = f2fma(a1, v1b.y, acc[i][3]);
                }
            }
        }

        // epilogue: relu(gcn) + residual, scattered fp32 stores
        #pragma unroll
        for (int i = 0; i < 4; ++i) {
            if (!nvld[i]) continue;
            int n = ni[i];
            float xr0 = xs[1 * NV + n];   // f=0, s=1  -> x[b,0,n,t]
            float xr1 = xs[4 * NV + n];   // f=1, s=1
            float xr2 = xs[7 * NV + n];   // f=2, s=1
            #pragma unroll
            for (int p = 0; p < 4; ++p) {
                float2 g = f2un(acc[i][p]);
                int o0 = o8 + 2 * p;
                float r0 = wrb[o0] + xr0 * wres[o0 * 3 + 0]
                                   + xr1 * wres[o0 * 3 + 1]
                                   + xr2 * wres[o0 * 3 + 2];
                float r1 = wrb[o0 + 1] + xr0 * wres[(o0 + 1) * 3 + 0]
                                       + xr1 * wres[(o0 + 1) * 3 + 1]
                                       + xr2 * wres[(o0 + 1) * 3 + 2];
                out[((size_t)(b * OO + o0)     * NV + n) * TTq + t] = fmaxf(g.x, 0.0f) + r0;
                out[((size_t)(b * OO + o0 + 1) * NV + n) * TTq + t] = fmaxf(g.y, 0.0f) + r1;
            }
        }
    }
}

extern "C" void kernel_launch(void* const* d_in, const int* in_sizes, int n_in,
                              void* d_out, int out_size)
{
    (void)in_sizes; (void)n_in; (void)out_size;
    const float* x      = (const float*)d_in[0];
    // d_in[1] = adj (unused by forward)
    const float* cheb   = (const float*)d_in[2];
    const float* conv_w = (const float*)d_in[3];
    const float* conv_b = (const float*)d_in[4];
    const float* theta  = (const float*)d_in[5];
    const float* res_w  = (const float*)d_in[6];
    const float* res_b  = (const float*)d_in[7];
    float* out = (float*)d_out;

    cudaFuncSetAttribute(stgcn_fused_kernel,
                         cudaFuncAttributeMaxDynamicSharedMemorySize, SMEM_BYTES);

    dim3 grid(TTq, Bq);   // 288 x 16 = 4608 CTAs, one per (b, t)
    stgcn_fused_kernel<<<grid, 256, SMEM_BYTES>>>(
        x, cheb, conv_w, conv_b, theta, res_w, res_b, out);
}

// round 4
// speedup vs baseline: 1.2051x; 1.2051x over previous
#include <cuda_runtime.h>

// ---------------------------------------------------------------------------
// Fused spatio-temporal GCN layer, one CTA per (b, t), 2 CTAs/SM.
//   prep  : chebTd[k][m][n] = dup(cheb[k][n][m])  (float2, n padded to 176)
//   stage 0: x slice + weights -> smem
//   stage 1: temporal conv + ReLU -> TmT[c][m] (transposed, smem)
//   per k : stage 2: Vk[m][o] = sum_c TmT[c][m] * theta_k[c][o]  (smem)
//           stage 3: acc[n][o] += sum_m chebTd[k][m][n] * Vk[m][o]
//   epilogue: out = relu(acc) + residual
// All GEMM FMAs are packed fma.rn.f32x2; cheb scalars arrive pre-duplicated.
// ---------------------------------------------------------------------------

#define Bq   16
#define FINq 3
#define NV   170
#define NP   176      // padded n for chebTd
#define TTq  288
#define HH   64
#define OO   64
#define KK   3
#define NG   29       // row groups (29*6 = 174 >= 170)
#define RPT  6        // rows per thread

typedef unsigned long long ull;

__device__ __forceinline__ ull f2fma(ull a, ull b, ull c) {
    ull d;
    asm("fma.rn.f32x2 %0, %1, %2, %3;" : "=l"(d) : "l"(a), "l"(b), "l"(c));
    return d;
}
__device__ __forceinline__ ull f2dup(float a) {
    ull d;
    asm("mov.b64 %0, {%1, %1};" : "=l"(d) : "f"(a));
    return d;
}
__device__ __forceinline__ float2 f2un(ull p) {
    float2 r;
    asm("mov.b64 {%0, %1}, %2;" : "=f"(r.x), "=f"(r.y) : "l"(p));
    return r;
}

// pre-transposed, value-duplicated Chebyshev polys: [k][m][n] of float2{c,c}
__device__ __align__(16) float2 g_chebTd[KK * NV * NP];

__global__ void prep_chebTd(const float* __restrict__ cheb) {
    int idx = blockIdx.x * 256 + threadIdx.x;
    if (idx >= KK * NV * NP) return;
    int n  = idx % NP;
    int km = idx / NP;
    int m  = km % NV;
    int k  = km / NV;
    float v = (n < NV) ? cheb[((size_t)k * NV + n) * NV + m] : 0.0f;
    g_chebTd[idx] = make_float2(v, v);
}

// shared memory layout (float offsets)
#define XS_OFF   0                       // 3*3*170 = 1530
#define WC_OFF   1530                    // conv_w 576
#define WCB_OFF  2106                    // conv_b 64
#define WRES_OFF 2170                    // res_w 192
#define WRB_OFF  2362                    // res_b 64
#define TMT_OFF  2432                    // TmT[c][m]: 64*170 = 10880
#define V_OFF    (TMT_OFF + HH * NV)     // 13312; Vk 170*64 = 10880
#define SMEM_FLOATS (V_OFF + NV * OO)    // 24192
#define SMEM_BYTES  (SMEM_FLOATS * 4)    // 96768 bytes -> 2 CTAs/SM

__global__ void __launch_bounds__(256, 2)
stgcn_fused_kernel(const float* __restrict__ x,
                   const float* __restrict__ theta,
                   const float* __restrict__ conv_w,
                   const float* __restrict__ conv_b,
                   const float* __restrict__ res_w,
                   const float* __restrict__ res_b,
                   float* __restrict__ out)
{
    extern __shared__ float sm[];
    float* xs   = sm + XS_OFF;
    float* wc   = sm + WC_OFF;
    float* wcb  = sm + WCB_OFF;
    float* wres = sm + WRES_OFF;
    float* wrb  = sm + WRB_OFF;
    float* TmT  = sm + TMT_OFF;
    float* Vv   = sm + V_OFF;

    const int t   = blockIdx.x;
    const int b   = blockIdx.y;
    const int tid = threadIdx.x;

    // ---------------- stage 0: smem loads ----------------
    for (int i = tid; i < FINq * 3 * NV; i += 256) {
        int f = i / (3 * NV);
        int r = i - f * (3 * NV);
        int s = r / NV;
        int m = r - s * NV;
        int tt = t + s - 1;
        float v = 0.0f;
        if (tt >= 0 && tt < TTq)
            v = x[((size_t)(b * FINq + f) * NV + m) * TTq + tt];
        xs[i] = v;                       // (f*3+s)*NV + m
    }
    for (int i = tid; i < HH * FINq * 3; i += 256) wc[i] = conv_w[i];
    for (int i = tid; i < OO * FINq;     i += 256) wres[i] = res_w[i];
    if (tid < HH)                    wcb[tid]      = conv_b[tid];
    else if (tid >= 64 && tid < 128) wrb[tid - 64] = res_b[tid - 64];
    __syncthreads();

    // ---------------- stage 1: temporal conv + ReLU -> TmT[c][m] ----------------
    for (int idx = tid; idx < NV * HH; idx += 256) {
        int m = idx >> 6;
        int c = idx & 63;
        float v = wcb[c];
        #pragma unroll
        for (int f = 0; f < FINq; ++f)
            #pragma unroll
            for (int s = 0; s < 3; ++s)
                v = fmaf(xs[(f * 3 + s) * NV + m], wc[(c * FINq + f) * 3 + s], v);
        TmT[c * NV + m] = fmaxf(v, 0.0f);
    }

    const int tcol = tid & 7;
    const int g    = tid >> 3;          // 0..31; active when g < 29
    const int o8   = tcol * 8;
    const int n0   = g * RPT;
    const bool act = (g < NG);

    ull acc[RPT][4];
    #pragma unroll
    for (int i = 0; i < RPT; ++i)
        #pragma unroll
        for (int p = 0; p < 4; ++p) acc[i][p] = 0ull;

    for (int k = 0; k < KK; ++k) {
        __syncthreads();   // k=0: TmT ready; k>0: prior stage-3 readers done

        // ------------- stage 2: Vk = TmT^T @ theta_k (two 3-row halves) -------------
        if (act) {
            const float* th = theta + (size_t)k * HH * OO + o8;
            #pragma unroll
            for (int h = 0; h < 2; ++h) {
                const int mh = n0 + 3 * h;
                ull a2[3][4];
                #pragma unroll
                for (int i = 0; i < 3; ++i)
                    #pragma unroll
                    for (int p = 0; p < 4; ++p) a2[i][p] = 0ull;

                #pragma unroll 4
                for (int c = 0; c < HH; ++c) {
                    ulonglong2 ta = *(const ulonglong2*)(th + (size_t)c * OO);
                    ulonglong2 tb = *(const ulonglong2*)(th + (size_t)c * OO + 4);
                    const float* tr = TmT + c * NV + mh;
                    #pragma unroll
                    for (int i = 0; i < 3; ++i) {
                        ull aa = f2dup(tr[i]);
                        a2[i][0] = f2fma(aa, ta.x, a2[i][0]);
                        a2[i][1] = f2fma(aa, ta.y, a2[i][1]);
                        a2[i][2] = f2fma(aa, tb.x, a2[i][2]);
                        a2[i][3] = f2fma(aa, tb.y, a2[i][3]);
                    }
                }
                #pragma unroll
                for (int i = 0; i < 3; ++i) {
                    int m = mh + i;
                    if (m < NV) {
                        ulonglong2* dst = (ulonglong2*)(Vv + (size_t)m * OO + o8);
                        dst[0] = make_ulonglong2(a2[i][0], a2[i][1]);
                        dst[1] = make_ulonglong2(a2[i][2], a2[i][3]);
                    }
                }
            }
        }
        __syncthreads();

        // ------------- stage 3: acc += chebTd_k[:, n0..n0+5]^T-style MACs -------------
        if (act) {
            const float2* chp = g_chebTd + (size_t)k * NV * NP + n0;
            #pragma unroll 2
            for (int m = 0; m < NV; ++m) {
                const ulonglong2* cp = (const ulonglong2*)(chp + (size_t)m * NP);
                ulonglong2 c01 = cp[0];     // dup'd cheb[n0], cheb[n0+1]
                ulonglong2 c23 = cp[1];
                ulonglong2 c45 = cp[2];
                const float* vp = Vv + (size_t)m * OO + o8;
                ulonglong2 va = *(const ulonglong2*)(vp);
                ulonglong2 vb = *(const ulonglong2*)(vp + 4);

                acc[0][0] = f2fma(c01.x, va.x, acc[0][0]);
                acc[0][1] = f2fma(c01.x, va.y, acc[0][1]);
                acc[0][2] = f2fma(c01.x, vb.x, acc[0][2]);
                acc[0][3] = f2fma(c01.x, vb.y, acc[0][3]);
                acc[1][0] = f2fma(c01.y, va.x, acc[1][0]);
                acc[1][1] = f2fma(c01.y, va.y, acc[1][1]);
                acc[1][2] = f2fma(c01.y, vb.x, acc[1][2]);
                acc[1][3] = f2fma(c01.y, vb.y, acc[1][3]);
                acc[2][0] = f2fma(c23.x, va.x, acc[2][0]);
                acc[2][1] = f2fma(c23.x, va.y, acc[2][1]);
                acc[2][2] = f2fma(c23.x, vb.x, acc[2][2]);
                acc[2][3] = f2fma(c23.x, vb.y, acc[2][3]);
                acc[3][0] = f2fma(c23.y, va.x, acc[3][0]);
                acc[3][1] = f2fma(c23.y, va.y, acc[3][1]);
                acc[3][2] = f2fma(c23.y, vb.x, acc[3][2]);
                acc[3][3] = f2fma(c23.y, vb.y, acc[3][3]);
                acc[4][0] = f2fma(c45.x, va.x, acc[4][0]);
                acc[4][1] = f2fma(c45.x, va.y, acc[4][1]);
                acc[4][2] = f2fma(c45.x, vb.x, acc[4][2]);
                acc[4][3] = f2fma(c45.x, vb.y, acc[4][3]);
                acc[5][0] = f2fma(c45.y, va.x, acc[5][0]);
                acc[5][1] = f2fma(c45.y, va.y, acc[5][1]);
                acc[5][2] = f2fma(c45.y, vb.x, acc[5][2]);
                acc[5][3] = f2fma(c45.y, vb.y, acc[5][3]);
            }
        }
    }

    // ---------------- epilogue: relu(gcn) + residual ----------------
    if (act) {
        #pragma unroll
        for (int i = 0; i < RPT; ++i) {
            int n = n0 + i;
            if (n >= NV) break;
            float xr0 = xs[1 * NV + n];
            float xr1 = xs[4 * NV + n];
            float xr2 = xs[7 * NV + n];
            #pragma unroll
            for (int p = 0; p < 4; ++p) {
                float2 gv = f2un(acc[i][p]);
                int o0 = o8 + 2 * p;
                float r0 = wrb[o0] + xr0 * wres[o0 * 3 + 0]
                                   + xr1 * wres[o0 * 3 + 1]
                                   + xr2 * wres[o0 * 3 + 2];
                float r1 = wrb[o0 + 1] + xr0 * wres[(o0 + 1) * 3 + 0]
                                       + xr1 * wres[(o0 + 1) * 3 + 1]
                                       + xr2 * wres[(o0 + 1) * 3 + 2];
                out[((size_t)(b * OO + o0)     * NV + n) * TTq + t] = fmaxf(gv.x, 0.0f) + r0;
                out[((size_t)(b * OO + o0 + 1) * NV + n) * TTq + t] = fmaxf(gv.y, 0.0f) + r1;
            }
        }
    }
}

extern "C" void kernel_launch(void* const* d_in, const int* in_sizes, int n_in,
                              void* d_out, int out_size)
{
    (void)in_sizes; (void)n_in; (void)out_size;
    const float* x      = (const float*)d_in[0];
    // d_in[1] = adj (unused by forward)
    const float* cheb   = (const float*)d_in[2];
    const float* conv_w = (const float*)d_in[3];
    const float* conv_b = (const float*)d_in[4];
    const float* theta  = (const float*)d_in[5];
    const float* res_w  = (const float*)d_in[6];
    const float* res_b  = (const float*)d_in[7];
    float* out = (float*)d_out;

    // build transposed+duplicated cheb (tiny; runs every launch, deterministic)
    prep_chebTd<<<(KK * NV * NP + 255) / 256, 256>>>(cheb);

    cudaFuncSetAttribute(stgcn_fused_kernel,
                         cudaFuncAttributeMaxDynamicSharedMemorySize, SMEM_BYTES);

    dim3 grid(TTq, Bq);   // 4608 CTAs, one per (b, t)
    stgcn_fused_kernel<<<grid, 256, SMEM_BYTES>>>(
        x, theta, conv_w, conv_b, res_w, res_b, out);
}

// round 5
// speedup vs baseline: 1.5146x; 1.2568x over previous
#include <cuda_runtime.h>

// ---------------------------------------------------------------------------
// Fused spatio-temporal GCN, one 256-thread CTA per (b,t), 1 CTA/SM.
// All stage-2/3 operands live in smem; theta/cheb k-slices are cp.async
// prefetched behind compute so the inner loops are pure LDS + fma.rn.f32x2.
// ---------------------------------------------------------------------------

#define Bq   16
#define FINq 3
#define NV   170
#define MPAD 174          // cheb row pad (bank-conflict-free, 8B-aligned rows)
#define TTq  288
#define HH   64
#define OO   64
#define KK   3
#define RPT  6            // n-rows per thread (32 groups x 6 = 192 >= 170)

typedef unsigned long long ull;

__device__ __forceinline__ ull f2fma(ull a, ull b, ull c) {
    ull d;
    asm("fma.rn.f32x2 %0, %1, %2, %3;" : "=l"(d) : "l"(a), "l"(b), "l"(c));
    return d;
}
__device__ __forceinline__ ull f2dup(float a) {
    ull d;
    asm("mov.b64 %0, {%1, %1};" : "=l"(d) : "f"(a));
    return d;
}
__device__ __forceinline__ float2 f2un(ull p) {
    float2 r;
    asm("mov.b64 {%0, %1}, %2;" : "=f"(r.x), "=f"(r.y) : "l"(p));
    return r;
}
__device__ __forceinline__ unsigned s2u(const void* p) {
    unsigned a;
    asm("{ .reg .u64 t; cvta.to.shared.u64 t, %1; cvt.u32.u64 %0, t; }"
        : "=r"(a) : "l"(p));
    return a;
}
#define CPA16(d, s) asm volatile("cp.async.cg.shared.global [%0], [%1], 16;" \
                                 :: "r"(d), "l"(s) : "memory")
#define CPCOMMIT()  asm volatile("cp.async.commit_group;" ::: "memory")
#define CPWAIT(n)   asm volatile("cp.async.wait_group %0;" :: "n"(n) : "memory")

// cheb rows padded 170 -> 174, contiguous per k-slice (cp.async-friendly)
__device__ __align__(16) float g_chebT[KK * NV * MPAD];

__global__ void prep_chebT(const float* __restrict__ cheb) {
    int idx = blockIdx.x * 256 + threadIdx.x;
    if (idx >= KK * NV * MPAD) return;
    int j  = idx % MPAD;
    int kn = idx / MPAD;
    g_chebT[idx] = (j < NV) ? cheb[kn * NV + j] : 0.0f;
}

// shared memory layout (float offsets)
#define XS_OFF   0                       // 3*3*170 = 1530
#define WC_OFF   1530                    // 576
#define WCB_OFF  2106                    // 64
#define WRES_OFF 2170                    // 192
#define WRB_OFF  2362                    // 64
#define TMT_OFF  2432                    // TmT[c][m] 64*170 = 10880
#define V_OFF    (TMT_OFF + HH * NV)     // 13312; V[m][o] 170*64 = 10880
#define THS_OFF  (V_OFF + NV * OO)       // 24192; thetaS 64*64 = 4096
#define CHS_OFF  (THS_OFF + HH * OO)     // 28288; chebS[n][MPAD] = 29580
#define SMEM_FLOATS (CHS_OFF + NV * MPAD)    // 57868
#define SMEM_BYTES  (SMEM_FLOATS * 4)        // 231472 B (<= 227 KB limit)

#define CHEB_CHUNKS ((NV * MPAD) / 4)    // 7395 x 16B
#define THETA_CHUNKS ((HH * OO) / 4)     // 1024 x 16B

__global__ void __launch_bounds__(256, 1)
stgcn_fused_kernel(const float* __restrict__ x,
                   const float* __restrict__ theta,
                   const float* __restrict__ conv_w,
                   const float* __restrict__ conv_b,
                   const float* __restrict__ res_w,
                   const float* __restrict__ res_b,
                   float* __restrict__ out)
{
    extern __shared__ float sm[];
    float* xs   = sm + XS_OFF;
    float* wc   = sm + WC_OFF;
    float* wcb  = sm + WCB_OFF;
    float* wres = sm + WRES_OFF;
    float* wrb  = sm + WRB_OFF;
    float* TmT  = sm + TMT_OFF;
    float* Vv   = sm + V_OFF;
    float* ths  = sm + THS_OFF;
    float* chs  = sm + CHS_OFF;
    const unsigned ths_u = s2u(ths);
    const unsigned chs_u = s2u(chs);

    const int t   = blockIdx.x;
    const int b   = blockIdx.y;
    const int tid = threadIdx.x;

    // ---- prefetch theta[0] (group A) and cheb[0] (group B) ----
    for (int i = tid; i < THETA_CHUNKS; i += 256)
        CPA16(ths_u + i * 16, theta + (size_t)i * 4);
    CPCOMMIT();
    for (int i = tid; i < CHEB_CHUNKS; i += 256)
        CPA16(chs_u + i * 16, g_chebT + (size_t)i * 4);
    CPCOMMIT();

    // ---------------- stage 0: xs + small weights ----------------
    for (int i = tid; i < FINq * 3 * NV; i += 256) {
        int f = i / (3 * NV);
        int r = i - f * (3 * NV);
        int s = r / NV;
        int m = r - s * NV;
        int tt = t + s - 1;
        float v = 0.0f;
        if (tt >= 0 && tt < TTq)
            v = x[((size_t)(b * FINq + f) * NV + m) * TTq + tt];
        xs[i] = v;                       // (f*3+s)*NV + m
    }
    for (int i = tid; i < HH * FINq * 3; i += 256) wc[i] = conv_w[i];
    for (int i = tid; i < OO * FINq;     i += 256) wres[i] = res_w[i];
    if (tid < HH)                    wcb[tid]      = conv_b[tid];
    else if (tid >= 64 && tid < 128) wrb[tid - 64] = res_b[tid - 64];
    __syncthreads();

    // ---------------- stage 1: temporal conv + ReLU -> TmT[c][m] ----------------
    for (int idx = tid; idx < NV * HH; idx += 256) {
        int m = idx >> 6;
        int c = idx & 63;
        float v = wcb[c];
        #pragma unroll
        for (int f = 0; f < FINq; ++f)
            #pragma unroll
            for (int s = 0; s < 3; ++s)
                v = fmaf(xs[(f * 3 + s) * NV + m], wc[(c * FINq + f) * 3 + s], v);
        TmT[c * NV + m] = fmaxf(v, 0.0f);
    }
    CPWAIT(1);          // theta[0] landed (cheb[0] may still be in flight)
    __syncthreads();    // TmT + thetaS visible to all

    const int tcol = tid & 7;
    const int g    = tid >> 3;           // 0..31, active while rows < NV
    const int o8   = tcol * 8;
    const int n0   = g * RPT;
    const bool act = (n0 < NV);          // g <= 28

    int nr[RPT];
    #pragma unroll
    for (int i = 0; i < RPT; ++i) nr[i] = (n0 + i < NV) ? (n0 + i) : (NV - 1);

    ull acc[RPT][4];
    #pragma unroll
    for (int i = 0; i < RPT; ++i)
        #pragma unroll
        for (int p = 0; p < 4; ++p) acc[i][p] = 0ull;

    for (int k = 0; k < KK; ++k) {
        // ------------- stage 2: V = TmT^T @ thetaS (smem-only) -------------
        if (act) {
            ull a2[RPT][4];
            #pragma unroll
            for (int i = 0; i < RPT; ++i)
                #pragma unroll
                for (int p = 0; p < 4; ++p) a2[i][p] = 0ull;

            #pragma unroll 2
            for (int c = 0; c < HH; ++c) {
                const float* tr = ths + c * OO + o8;
                ulonglong2 ta = *(const ulonglong2*)tr;
                ulonglong2 tb = *(const ulonglong2*)(tr + 4);
                const float* tm = TmT + c * NV;
                #pragma unroll
                for (int i = 0; i < RPT; ++i) {
                    ull aa = f2dup(tm[nr[i]]);
                    a2[i][0] = f2fma(aa, ta.x, a2[i][0]);
                    a2[i][1] = f2fma(aa, ta.y, a2[i][1]);
                    a2[i][2] = f2fma(aa, tb.x, a2[i][2]);
                    a2[i][3] = f2fma(aa, tb.y, a2[i][3]);
                }
            }
            #pragma unroll
            for (int i = 0; i < RPT; ++i) {
                int m = n0 + i;
                if (m < NV) {
                    ulonglong2* dst = (ulonglong2*)(Vv + (size_t)m * OO + o8);
                    dst[0] = make_ulonglong2(a2[i][0], a2[i][1]);
                    dst[1] = make_ulonglong2(a2[i][2], a2[i][3]);
                }
            }
        }
        CPWAIT(0);          // chebS[k] landed
        __syncthreads();    // V + chebS visible

        // prefetch theta[k+1] now (thetaS consumers done; covered by stage 3)
        if (k < KK - 1) {
            const float* tsrc = theta + (size_t)(k + 1) * HH * OO;
            for (int i = tid; i < THETA_CHUNKS; i += 256)
                CPA16(ths_u + i * 16, tsrc + (size_t)i * 4);
            CPCOMMIT();
        }

        // ------------- stage 3: acc += chebS[n][:] * V[:][o] (smem-only) -------------
        if (act) {
            const float* cr0 = chs + (size_t)nr[0] * MPAD;
            const float* cr1 = chs + (size_t)nr[1] * MPAD;
            const float* cr2 = chs + (size_t)nr[2] * MPAD;
            const float* cr3 = chs + (size_t)nr[3] * MPAD;
            const float* cr4 = chs + (size_t)nr[4] * MPAD;
            const float* cr5 = chs + (size_t)nr[5] * MPAD;
            #pragma unroll 5
            for (int m = 0; m < NV; m += 2) {
                ull cp[RPT];
                cp[0] = *(const ull*)(cr0 + m);
                cp[1] = *(const ull*)(cr1 + m);
                cp[2] = *(const ull*)(cr2 + m);
                cp[3] = *(const ull*)(cr3 + m);
                cp[4] = *(const ull*)(cr4 + m);
                cp[5] = *(const ull*)(cr5 + m);
                const float* vp = Vv + (size_t)m * OO + o8;
                ulonglong2 va = *(const ulonglong2*)(vp);
                ulonglong2 vb = *(const ulonglong2*)(vp + 4);
                ulonglong2 wa = *(const ulonglong2*)(vp + OO);
                ulonglong2 wb = *(const ulonglong2*)(vp + OO + 4);
                #pragma unroll
                for (int i = 0; i < RPT; ++i) {
                    float2 cc = f2un(cp[i]);
                    ull a0 = f2dup(cc.x);
                    ull a1 = f2dup(cc.y);
                    acc[i][0] = f2fma(a0, va.x, acc[i][0]);
                    acc[i][1] = f2fma(a0, va.y, acc[i][1]);
                    acc[i][2] = f2fma(a0, vb.x, acc[i][2]);
                    acc[i][3] = f2fma(a0, vb.y, acc[i][3]);
                    acc[i][0] = f2fma(a1, wa.x, acc[i][0]);
                    acc[i][1] = f2fma(a1, wa.y, acc[i][1]);
                    acc[i][2] = f2fma(a1, wb.x, acc[i][2]);
                    acc[i][3] = f2fma(a1, wb.y, acc[i][3]);
                }
            }
        }
        __syncthreads();    // chebS readers done

        // prefetch cheb[k+1]; wait theta[k+1] (already landed during stage 3)
        if (k < KK - 1) {
            const float* csrc = g_chebT + (size_t)(k + 1) * NV * MPAD;
            for (int i = tid; i < CHEB_CHUNKS; i += 256)
                CPA16(chs_u + i * 16, csrc + (size_t)i * 4);
            CPCOMMIT();
            CPWAIT(1);      // all but newest (cheb[k+1]) done -> theta[k+1] ready
            __syncthreads();
        }
    }

    // ---------------- epilogue: relu(gcn) + residual ----------------
    if (act) {
        #pragma unroll
        for (int i = 0; i < RPT; ++i) {
            int n = n0 + i;
            if (n >= NV) break;
            float xr0 = xs[1 * NV + n];
            float xr1 = xs[4 * NV + n];
            float xr2 = xs[7 * NV + n];
            #pragma unroll
            for (int p = 0; p < 4; ++p) {
                float2 gv = f2un(acc[i][p]);
                int o0 = o8 + 2 * p;
                float r0 = wrb[o0] + xr0 * wres[o0 * 3 + 0]
                                   + xr1 * wres[o0 * 3 + 1]
                                   + xr2 * wres[o0 * 3 + 2];
                float r1 = wrb[o0 + 1] + xr0 * wres[(o0 + 1) * 3 + 0]
                                       + xr1 * wres[(o0 + 1) * 3 + 1]
                                       + xr2 * wres[(o0 + 1) * 3 + 2];
                out[((size_t)(b * OO + o0)     * NV + n) * TTq + t] = fmaxf(gv.x, 0.0f) + r0;
                out[((size_t)(b * OO + o0 + 1) * NV + n) * TTq + t] = fmaxf(gv.y, 0.0f) + r1;
            }
        }
    }
}

extern "C" void kernel_launch(void* const* d_in, const int* in_sizes, int n_in,
                              void* d_out, int out_size)
{
    (void)in_sizes; (void)n_in; (void)out_size;
    const float* x      = (const float*)d_in[0];
    // d_in[1] = adj (unused by forward)
    const float* cheb   = (const float*)d_in[2];
    const float* conv_w = (const float*)d_in[3];
    const float* conv_b = (const float*)d_in[4];
    const float* theta  = (const float*)d_in[5];
    const float* res_w  = (const float*)d_in[6];
    const float* res_b  = (const float*)d_in[7];
    float* out = (float*)d_out;

    prep_chebT<<<(KK * NV * MPAD + 255) / 256, 256>>>(cheb);

    cudaFuncSetAttribute(stgcn_fused_kernel,
                         cudaFuncAttributeMaxDynamicSharedMemorySize, SMEM_BYTES);

    dim3 grid(TTq, Bq);   // 4608 CTAs, one per (b, t)
    stgcn_fused_kernel<<<grid, 256, SMEM_BYTES>>>(
        x, theta, conv_w, conv_b, res_w, res_b, out);
}

// round 6
// speedup vs baseline: 1.5352x; 1.0136x over previous
#include <cuda_runtime.h>

// ---------------------------------------------------------------------------
// Fused spatio-temporal GCN, one 256-thread CTA per (b,t), 1 CTA/SM.
// All stage-2/3 smem reads are LDS.128 (4-wide over the reduction dim);
// theta/cheb k-slices cp.async-prefetched behind compute; cheb slice shares
// smem with the x slice (residual x kept in registers).
// ---------------------------------------------------------------------------

#define Bq   16
#define FINq 3
#define NV   170
#define MPAD 172          // cheb row pad: 16B rows, 6*172%32=8 -> no conflicts
#define TMP  68           // Tm row pad:   16B rows, 6*68%32=24 -> no conflicts
#define TTq  288
#define HH   64
#define OO   64
#define KK   3
#define RPT  6            // n-rows per thread

typedef unsigned long long ull;

__device__ __forceinline__ ull f2fma(ull a, ull b, ull c) {
    ull d;
    asm("fma.rn.f32x2 %0, %1, %2, %3;" : "=l"(d) : "l"(a), "l"(b), "l"(c));
    return d;
}
__device__ __forceinline__ ull f2dup(float a) {
    ull d;
    asm("mov.b64 %0, {%1, %1};" : "=l"(d) : "f"(a));
    return d;
}
__device__ __forceinline__ float2 f2un(ull p) {
    float2 r;
    asm("mov.b64 {%0, %1}, %2;" : "=f"(r.x), "=f"(r.y) : "l"(p));
    return r;
}
__device__ __forceinline__ unsigned s2u(const void* p) {
    unsigned a;
    asm("{ .reg .u64 t; cvta.to.shared.u64 t, %1; cvt.u32.u64 %0, t; }"
        : "=r"(a) : "l"(p));
    return a;
}
#define CPA16(d, s) asm volatile("cp.async.cg.shared.global [%0], [%1], 16;" \
                                 :: "r"(d), "l"(s) : "memory")
#define CPCOMMIT()  asm volatile("cp.async.commit_group;" ::: "memory")
#define CPWAIT(n)   asm volatile("cp.async.wait_group %0;" :: "n"(n) : "memory")

__device__ __align__(16) float g_chebT[KK * NV * MPAD];

__global__ void prep_chebT(const float* __restrict__ cheb) {
    int idx = blockIdx.x * 256 + threadIdx.x;
    if (idx >= KK * NV * MPAD) return;
    int j  = idx % MPAD;
    int kn = idx / MPAD;
    g_chebT[idx] = (j < NV) ? cheb[kn * NV + j] : 0.0f;
}

// shared memory layout (float offsets)
#define WC_OFF   0                        // conv_w 576
#define WCB_OFF  576                      // conv_b 64
#define WRES_OFF 640                      // res_w 192
#define WRB_OFF  832                      // res_b 64
#define CHS_OFF  896                      // cheb slice 170*172 = 29240
#define XS_OFF   896                      // x slice 1530 (OVERLAPS chs; freed
                                          //  to regs before cheb[0] lands)
#define TM_OFF   (CHS_OFF + NV * MPAD)    // 30136; Tm[m][TMP] 170*68 = 11560
#define V_OFF    (TM_OFF + NV * TMP)      // 41696; V[m][64] = 10880
#define THS_OFF  (V_OFF + NV * OO)        // 52576; thetaS 64*64 = 4096
#define SMEM_FLOATS (THS_OFF + HH * OO)   // 56672
#define SMEM_BYTES  (SMEM_FLOATS * 4)     // 226688 B (<= 227 KB)

#define CHEB_CHUNKS  ((NV * MPAD) / 4)    // 7310 x 16B
#define THETA_CHUNKS ((HH * OO) / 4)      // 1024 x 16B

__global__ void __launch_bounds__(256, 1)
stgcn_fused_kernel(const float* __restrict__ x,
                   const float* __restrict__ theta,
                   const float* __restrict__ conv_w,
                   const float* __restrict__ conv_b,
                   const float* __restrict__ res_w,
                   const float* __restrict__ res_b,
                   float* __restrict__ out)
{
    extern __shared__ float sm[];
    float* wc   = sm + WC_OFF;
    float* wcb  = sm + WCB_OFF;
    float* wres = sm + WRES_OFF;
    float* wrb  = sm + WRB_OFF;
    float* xs   = sm + XS_OFF;
    float* chs  = sm + CHS_OFF;
    float* Tm   = sm + TM_OFF;
    float* Vv   = sm + V_OFF;
    float* ths  = sm + THS_OFF;
    const unsigned ths_u = s2u(ths);
    const unsigned chs_u = s2u(chs);

    const int t   = blockIdx.x;
    const int b   = blockIdx.y;
    const int tid = threadIdx.x;

    // ---- prefetch theta[0] ----
    for (int i = tid; i < THETA_CHUNKS; i += 256)
        CPA16(ths_u + i * 16, theta + (size_t)i * 4);
    CPCOMMIT();

    // ---------------- stage 0: xs + small weights ----------------
    for (int i = tid; i < FINq * 3 * NV; i += 256) {
        int f = i / (3 * NV);
        int r = i - f * (3 * NV);
        int s = r / NV;
        int m = r - s * NV;
        int tt = t + s - 1;
        float v = 0.0f;
        if (tt >= 0 && tt < TTq)
            v = x[((size_t)(b * FINq + f) * NV + m) * TTq + tt];
        xs[i] = v;                       // (f*3+s)*NV + m
    }
    for (int i = tid; i < HH * FINq * 3; i += 256) wc[i] = conv_w[i];
    for (int i = tid; i < OO * FINq;     i += 256) wres[i] = res_w[i];
    if (tid < HH)                    wcb[tid]      = conv_b[tid];
    else if (tid >= 64 && tid < 128) wrb[tid - 64] = res_b[tid - 64];
    __syncthreads();

    // ---------------- stage 1: temporal conv + ReLU -> Tm[m][c] ----------------
    for (int idx = tid; idx < NV * HH; idx += 256) {
        int m = idx >> 6;
        int c = idx & 63;
        float v = wcb[c];
        #pragma unroll
        for (int f = 0; f < FINq; ++f)
            #pragma unroll
            for (int s = 0; s < 3; ++s)
                v = fmaf(xs[(f * 3 + s) * NV + m], wc[(c * FINq + f) * 3 + s], v);
        Tm[m * TMP + c] = fmaxf(v, 0.0f);
    }

    const int tcol = tid & 7;
    const int g    = tid >> 3;           // 0..31
    const int o8   = tcol * 8;
    const int n0   = g * RPT;
    const bool act = (n0 < NV);          // g <= 28

    int nr[RPT];
    #pragma unroll
    for (int i = 0; i < RPT; ++i) nr[i] = (n0 + i < NV) ? (n0 + i) : (NV - 1);

    // snapshot residual x into registers (xs region is recycled for chs)
    float xr[RPT][3];
    #pragma unroll
    for (int i = 0; i < RPT; ++i) {
        xr[i][0] = xs[1 * NV + nr[i]];
        xr[i][1] = xs[4 * NV + nr[i]];
        xr[i][2] = xs[7 * NV + nr[i]];
    }
    __syncthreads();     // all xs reads + Tm writes done

    // ---- prefetch cheb[0] into chs (overwrites xs region) ----
    for (int i = tid; i < CHEB_CHUNKS; i += 256)
        CPA16(chs_u + i * 16, g_chebT + (size_t)i * 4);
    CPCOMMIT();
    CPWAIT(1);           // theta[0] landed
    __syncthreads();

    ull acc[RPT][4];
    #pragma unroll
    for (int i = 0; i < RPT; ++i)
        #pragma unroll
        for (int p = 0; p < 4; ++p) acc[i][p] = 0ull;

    for (int k = 0; k < KK; ++k) {
        // ------------- stage 2: V = Tm @ thetaS (LDS.128 both operands) -------------
        if (act) {
            ull a2[RPT][4];
            #pragma unroll
            for (int i = 0; i < RPT; ++i)
                #pragma unroll
                for (int p = 0; p < 4; ++p) a2[i][p] = 0ull;

            for (int c = 0; c < HH; c += 4) {
                ulonglong2 th0a = *(const ulonglong2*)(ths + (c + 0) * OO + o8);
                ulonglong2 th0b = *(const ulonglong2*)(ths + (c + 0) * OO + o8 + 4);
                ulonglong2 th1a = *(const ulonglong2*)(ths + (c + 1) * OO + o8);
                ulonglong2 th1b = *(const ulonglong2*)(ths + (c + 1) * OO + o8 + 4);
                ulonglong2 th2a = *(const ulonglong2*)(ths + (c + 2) * OO + o8);
                ulonglong2 th2b = *(const ulonglong2*)(ths + (c + 2) * OO + o8 + 4);
                ulonglong2 th3a = *(const ulonglong2*)(ths + (c + 3) * OO + o8);
                ulonglong2 th3b = *(const ulonglong2*)(ths + (c + 3) * OO + o8 + 4);
                #pragma unroll
                for (int i = 0; i < RPT; ++i) {
                    ulonglong2 tm4 = *(const ulonglong2*)(Tm + nr[i] * TMP + c);
                    float2 t01 = f2un(tm4.x);
                    float2 t23 = f2un(tm4.y);
                    ull d0 = f2dup(t01.x), d1 = f2dup(t01.y);
                    ull d2 = f2dup(t23.x), d3 = f2dup(t23.y);
                    a2[i][0] = f2fma(d0, th0a.x, a2[i][0]);
                    a2[i][1] = f2fma(d0, th0a.y, a2[i][1]);
                    a2[i][2] = f2fma(d0, th0b.x, a2[i][2]);
                    a2[i][3] = f2fma(d0, th0b.y, a2[i][3]);
                    a2[i][0] = f2fma(d1, th1a.x, a2[i][0]);
                    a2[i][1] = f2fma(d1, th1a.y, a2[i][1]);
                    a2[i][2] = f2fma(d1, th1b.x, a2[i][2]);
                    a2[i][3] = f2fma(d1, th1b.y, a2[i][3]);
                    a2[i][0] = f2fma(d2, th2a.x, a2[i][0]);
                    a2[i][1] = f2fma(d2, th2a.y, a2[i][1]);
                    a2[i][2] = f2fma(d2, th2b.x, a2[i][2]);
                    a2[i][3] = f2fma(d2, th2b.y, a2[i][3]);
                    a2[i][0] = f2fma(d3, th3a.x, a2[i][0]);
                    a2[i][1] = f2fma(d3, th3a.y, a2[i][1]);
                    a2[i][2] = f2fma(d3, th3b.x, a2[i][2]);
                    a2[i][3] = f2fma(d3, th3b.y, a2[i][3]);
                }
            }
            #pragma unroll
            for (int i = 0; i < RPT; ++i) {
                int m = n0 + i;
                if (m < NV) {
                    ulonglong2* dst = (ulonglong2*)(Vv + (size_t)m * OO + o8);
                    dst[0] = make_ulonglong2(a2[i][0], a2[i][1]);
                    dst[1] = make_ulonglong2(a2[i][2], a2[i][3]);
                }
            }
        }
        CPWAIT(0);          // chs[k] landed
        __syncthreads();    // V + chs visible to all

        // prefetch theta[k+1] (covered by stage 3)
        if (k < KK - 1) {
            const float* tsrc = theta + (size_t)(k + 1) * HH * OO;
            for (int i = tid; i < THETA_CHUNKS; i += 256)
                CPA16(ths_u + i * 16, tsrc + (size_t)i * 4);
            CPCOMMIT();
        }

        // ------------- stage 3: acc += chs[n][m] * V[m][o] (LDS.128 both) -------------
        if (act) {
            const float* cr0 = chs + (size_t)nr[0] * MPAD;
            const float* cr1 = chs + (size_t)nr[1] * MPAD;
            const float* cr2 = chs + (size_t)nr[2] * MPAD;
            const float* cr3 = chs + (size_t)nr[3] * MPAD;
            const float* cr4 = chs + (size_t)nr[4] * MPAD;
            const float* cr5 = chs + (size_t)nr[5] * MPAD;
            for (int m = 0; m < NV - 2; m += 4) {
                ulonglong2 cb[RPT];
                cb[0] = *(const ulonglong2*)(cr0 + m);
                cb[1] = *(const ulonglong2*)(cr1 + m);
                cb[2] = *(const ulonglong2*)(cr2 + m);
                cb[3] = *(const ulonglong2*)(cr3 + m);
                cb[4] = *(const ulonglong2*)(cr4 + m);
                cb[5] = *(const ulonglong2*)(cr5 + m);
                const float* vp = Vv + (size_t)m * OO + o8;
                ulonglong2 v0a = *(const ulonglong2*)(vp);
                ulonglong2 v0b = *(const ulonglong2*)(vp + 4);
                ulonglong2 v1a = *(const ulonglong2*)(vp + OO);
                ulonglong2 v1b = *(const ulonglong2*)(vp + OO + 4);
                ulonglong2 v2a = *(const ulonglong2*)(vp + 2 * OO);
                ulonglong2 v2b = *(const ulonglong2*)(vp + 2 * OO + 4);
                ulonglong2 v3a = *(const ulonglong2*)(vp + 3 * OO);
                ulonglong2 v3b = *(const ulonglong2*)(vp + 3 * OO + 4);
                #pragma unroll
                for (int i = 0; i < RPT; ++i) {
                    float2 c01 = f2un(cb[i].x);
                    float2 c23 = f2un(cb[i].y);
                    ull d0 = f2dup(c01.x), d1 = f2dup(c01.y);
                    ull d2 = f2dup(c23.x), d3 = f2dup(c23.y);
                    acc[i][0] = f2fma(d0, v0a.x, acc[i][0]);
                    acc[i][1] = f2fma(d0, v0a.y, acc[i][1]);
                    acc[i][2] = f2fma(d0, v0b.x, acc[i][2]);
                    acc[i][3] = f2fma(d0, v0b.y, acc[i][3]);
                    acc[i][0] = f2fma(d1, v1a.x, acc[i][0]);
                    acc[i][1] = f2fma(d1, v1a.y, acc[i][1]);
                    acc[i][2] = f2fma(d1, v1b.x, acc[i][2]);
                    acc[i][3] = f2fma(d1, v1b.y, acc[i][3]);
                    acc[i][0] = f2fma(d2, v2a.x, acc[i][0]);
                    acc[i][1] = f2fma(d2, v2a.y, acc[i][1]);
                    acc[i][2] = f2fma(d2, v2b.x, acc[i][2]);
                    acc[i][3] = f2fma(d2, v2b.y, acc[i][3]);
                    acc[i][0] = f2fma(d3, v3a.x, acc[i][0]);
                    acc[i][1] = f2fma(d3, v3a.y, acc[i][1]);
                    acc[i][2] = f2fma(d3, v3b.x, acc[i][2]);
                    acc[i][3] = f2fma(d3, v3b.y, acc[i][3]);
                }
            }
            // tail: m = 168, 169
            {
                const int m = 168;
                ull cp2[RPT];
                cp2[0] = *(const ull*)(cr0 + m);
                cp2[1] = *(const ull*)(cr1 + m);
                cp2[2] = *(const ull*)(cr2 + m);
                cp2[3] = *(const ull*)(cr3 + m);
                cp2[4] = *(const ull*)(cr4 + m);
                cp2[5] = *(const ull*)(cr5 + m);
                const float* vp = Vv + (size_t)m * OO + o8;
                ulonglong2 v0a = *(const ulonglong2*)(vp);
                ulonglong2 v0b = *(const ulonglong2*)(vp + 4);
                ulonglong2 v1a = *(const ulonglong2*)(vp + OO);
                ulonglong2 v1b = *(const ulonglong2*)(vp + OO + 4);
                #pragma unroll
                for (int i = 0; i < RPT; ++i) {
                    float2 cc = f2un(cp2[i]);
                    ull d0 = f2dup(cc.x), d1 = f2dup(cc.y);
                    acc[i][0] = f2fma(d0, v0a.x, acc[i][0]);
                    acc[i][1] = f2fma(d0, v0a.y, acc[i][1]);
                    acc[i][2] = f2fma(d0, v0b.x, acc[i][2]);
                    acc[i][3] = f2fma(d0, v0b.y, acc[i][3]);
                    acc[i][0] = f2fma(d1, v1a.x, acc[i][0]);
                    acc[i][1] = f2fma(d1, v1a.y, acc[i][1]);
                    acc[i][2] = f2fma(d1, v1b.x, acc[i][2]);
                    acc[i][3] = f2fma(d1, v1b.y, acc[i][3]);
                }
            }
        }
        __syncthreads();    // chs readers done before overwrite

        if (k < KK - 1) {
            const float* csrc = g_chebT + (size_t)(k + 1) * NV * MPAD;
            for (int i = tid; i < CHEB_CHUNKS; i += 256)
                CPA16(chs_u + i * 16, csrc + (size_t)i * 4);
            CPCOMMIT();
            CPWAIT(1);      // theta[k+1] ready (cheb[k+1] still in flight)
            __syncthreads();
        }
    }

    // ---------------- epilogue: relu(gcn) + residual ----------------
    if (act) {
        #pragma unroll
        for (int i = 0; i < RPT; ++i) {
            int n = n0 + i;
            if (n >= NV) break;
            #pragma unroll
            for (int p = 0; p < 4; ++p) {
                float2 gv = f2un(acc[i][p]);
                int o0 = o8 + 2 * p;
                float r0 = wrb[o0] + xr[i][0] * wres[o0 * 3 + 0]
                                   + xr[i][1] * wres[o0 * 3 + 1]
                                   + xr[i][2] * wres[o0 * 3 + 2];
                float r1 = wrb[o0 + 1] + xr[i][0] * wres[(o0 + 1) * 3 + 0]
                                       + xr[i][1] * wres[(o0 + 1) * 3 + 1]
                                       + xr[i][2] * wres[(o0 + 1) * 3 + 2];
                out[((size_t)(b * OO + o0)     * NV + n) * TTq + t] = fmaxf(gv.x, 0.0f) + r0;
                out[((size_t)(b * OO + o0 + 1) * NV + n) * TTq + t] = fmaxf(gv.y, 0.0f) + r1;
            }
        }
    }
}

extern "C" void kernel_launch(void* const* d_in, const int* in_sizes, int n_in,
                              void* d_out, int out_size)
{
    (void)in_sizes; (void)n_in; (void)out_size;
    const float* x      = (const float*)d_in[0];
    // d_in[1] = adj (unused by forward)
    const float* cheb   = (const float*)d_in[2];
    const float* conv_w = (const float*)d_in[3];
    const float* conv_b = (const float*)d_in[4];
    const float* theta  = (const float*)d_in[5];
    const float* res_w  = (const float*)d_in[6];
    const float* res_b  = (const float*)d_in[7];
    float* out = (float*)d_out;

    prep_chebT<<<(KK * NV * MPAD + 255) / 256, 256>>>(cheb);

    cudaFuncSetAttribute(stgcn_fused_kernel,
                         cudaFuncAttributeMaxDynamicSharedMemorySize, SMEM_BYTES);

    dim3 grid(TTq, Bq);   // 4608 CTAs, one per (b, t)
    stgcn_fused_kernel<<<grid, 256, SMEM_BYTES>>>(
        x, theta, conv_w, conv_b, res_w, res_b, out);
}